// round 4
// baseline (speedup 1.0000x reference)
#include <cuda_runtime.h>
#include <cuda_bf16.h>

#define N_NODES 50000
#define N_EDGES 800000
#define D 64

// Scratch (__device__ globals; atomics target harness memory only)
__device__ float g_dinv[N_NODES];
__device__ float g_norm[N_EDGES];
__device__ __align__(16) float g_h[N_NODES * D];   // GEMM output / message source

// ---------------------------------------------------------------------------
// Norm precompute. deg lives temporarily in out[0..N) (harness buffer).
// ---------------------------------------------------------------------------
__global__ void init_deg_kernel(float* __restrict__ deg) {
    int i = blockIdx.x * blockDim.x + threadIdx.x;
    if (i < N_NODES) deg[i] = 1.0f;  // self-loop weight
}

__global__ void accum_deg_kernel(const int* __restrict__ ei,
                                 const float* __restrict__ ew,
                                 float* deg) {
    int e = blockIdx.x * blockDim.x + threadIdx.x;
    if (e < N_EDGES) {
        int d = ei[N_EDGES + e];
        atomicAdd(&deg[d], ew[e]);
    }
}

__global__ void dinv_kernel(const float* __restrict__ deg) {
    int i = blockIdx.x * blockDim.x + threadIdx.x;
    if (i < N_NODES) g_dinv[i] = rsqrtf(deg[i]);  // deg >= 1 always
}

__global__ void norm_kernel(const int* __restrict__ ei,
                            const float* __restrict__ ew) {
    int e = blockIdx.x * blockDim.x + threadIdx.x;
    if (e < N_EDGES) {
        int s = ei[e];
        int d = ei[N_EDGES + e];
        g_norm[e] = g_dinv[s] * ew[e] * g_dinv[d];
    }
}

// ---------------------------------------------------------------------------
// GEMM: g_h = (relu?)(X) @ W   X:[N,64] W:[64,64]
// One thread per row; W broadcast from shared; 64 fp32 accumulators.
// ---------------------------------------------------------------------------
template <bool RELU_IN>
__global__ void gemm_kernel(const float* __restrict__ X,
                            const float* __restrict__ W) {
    __shared__ float Ws[D * D];
    int tid = threadIdx.x;
    for (int i = tid; i < D * D; i += 256) Ws[i] = W[i];
    __syncthreads();

    int r = blockIdx.x * 256 + tid;
    if (r >= N_NODES) return;

    const float* xr = X + (size_t)r * D;

    float acc[D];
#pragma unroll
    for (int c = 0; c < D; c++) acc[c] = 0.0f;

#pragma unroll 4
    for (int k = 0; k < D; k++) {
        float xv = xr[k];
        if (RELU_IN) xv = fmaxf(xv, 0.0f);
#pragma unroll
        for (int c = 0; c < D; c++) acc[c] = fmaf(xv, Ws[k * D + c], acc[c]);
    }

    float4* hp = (float4*)(g_h + (size_t)r * D);
#pragma unroll
    for (int c = 0; c < D / 4; c++)
        hp[c] = make_float4(acc[4 * c], acc[4 * c + 1], acc[4 * c + 2], acc[4 * c + 3]);
}

// ---------------------------------------------------------------------------
// agg = h * selfnorm + b  (self-loop + bias; fully overwrites out)
// ---------------------------------------------------------------------------
__global__ void init_agg_kernel(const float* __restrict__ b,
                                float* __restrict__ out) {
    int idx = blockIdx.x * blockDim.x + threadIdx.x;  // over N*16 float4s
    if (idx >= N_NODES * (D / 4)) return;
    int i = idx >> 4;
    int c = (idx & 15) << 2;
    float dv = g_dinv[i];
    float sn = dv * dv;
    float4 h = *(const float4*)&g_h[i * D + c];
    float4 o = make_float4(fmaf(h.x, sn, b[c + 0]), fmaf(h.y, sn, b[c + 1]),
                           fmaf(h.z, sn, b[c + 2]), fmaf(h.w, sn, b[c + 3]));
    float* op = out + (size_t)i * D + c;
    op[0] = o.x; op[1] = o.y; op[2] = o.z; op[3] = o.w;
}

// ---------------------------------------------------------------------------
// Edge scatter: out[dst] += h[src] * norm[e]
// 16 lanes per edge, float4 gather, 4 scalar fp32 atomics
// ---------------------------------------------------------------------------
__global__ void scatter_kernel(const int* __restrict__ ei,
                               float* out) {
    int t = blockIdx.x * blockDim.x + threadIdx.x;  // over E*16
    int e = t >> 4;
    if (e >= N_EDGES) return;
    int c = (t & 15) << 2;

    int s = ei[e];
    int d = ei[N_EDGES + e];
    float nrm = g_norm[e];

    float4 v = *(const float4*)&g_h[s * D + c];

    float* p = out + (size_t)d * D + c;
    atomicAdd(p + 0, v.x * nrm);
    atomicAdd(p + 1, v.y * nrm);
    atomicAdd(p + 2, v.z * nrm);
    atomicAdd(p + 3, v.w * nrm);
}

// ---------------------------------------------------------------------------
// Final ReLU in-place on out
// ---------------------------------------------------------------------------
__global__ void relu_out_kernel(float* out) {
    int idx = blockIdx.x * blockDim.x + threadIdx.x;  // over N*D
    if (idx >= N_NODES * D) return;
    float v = out[idx];
    out[idx] = fmaxf(v, 0.0f);
}

// ---------------------------------------------------------------------------
extern "C" void kernel_launch(void* const* d_in, const int* in_sizes, int n_in,
                              void* d_out, int out_size) {
    const float* x  = (const float*)d_in[0];
    const int*   ei = (const int*)d_in[1];
    const float* ew = (const float*)d_in[2];
    const float* W0 = (const float*)d_in[3];
    const float* b0 = (const float*)d_in[4];
    const float* W1 = (const float*)d_in[5];
    const float* b1 = (const float*)d_in[6];
    const float* W2 = (const float*)d_in[7];
    const float* b2 = (const float*)d_in[8];
    float* out = (float*)d_out;

    const int TB = 256;
    const int gN   = (N_NODES + TB - 1) / TB;             // 196
    const int gE   = (N_EDGES + TB - 1) / TB;             // 3125
    const int gN16 = (N_NODES * (D / 4) + TB - 1) / TB;   // 3125
    const int gE16 = (N_EDGES * 16 + TB - 1) / TB;        // 50000
    const int gND  = (N_NODES * D + TB - 1) / TB;         // 12500

    // norm precompute (deg scratch = out[0..N), overwritten by layer 0 later)
    init_deg_kernel<<<gN, TB>>>(out);
    accum_deg_kernel<<<gE, TB>>>(ei, ew, out);
    dinv_kernel<<<gN, TB>>>(out);
    norm_kernel<<<gE, TB>>>(ei, ew);

    // layer 0
    gemm_kernel<false><<<gN, TB>>>(x, W0);
    init_agg_kernel<<<gN16, TB>>>(b0, out);
    scatter_kernel<<<gE16, TB>>>(ei, out);

    // layer 1 (relu applied on read)
    gemm_kernel<true><<<gN, TB>>>(out, W1);
    init_agg_kernel<<<gN16, TB>>>(b1, out);
    scatter_kernel<<<gE16, TB>>>(ei, out);

    // layer 2
    gemm_kernel<true><<<gN, TB>>>(out, W2);
    init_agg_kernel<<<gN16, TB>>>(b2, out);
    scatter_kernel<<<gE16, TB>>>(ei, out);

    relu_out_kernel<<<gND, TB>>>(out);
}

// round 5
// speedup vs baseline: 1.9680x; 1.9680x over previous
#include <cuda_runtime.h>
#include <cuda_bf16.h>

#define N_NODES 50000
#define N_EDGES 800000
#define D 64

#define SCAN_CHUNK 512
#define N_CHUNKS ((N_NODES + SCAN_CHUNK - 1) / SCAN_CHUNK)  // 98

// ---------------------------------------------------------------------------
// Device scratch
// ---------------------------------------------------------------------------
__device__ float g_deg[N_NODES];
__device__ float g_dinv[N_NODES];
__device__ int   g_cnt[N_NODES];       // in-degree (edges only)
__device__ int   g_off[N_NODES];       // CSR row offsets (exclusive scan of cnt)
__device__ int   g_cur[N_NODES];       // fill cursors
__device__ int   g_bsum[N_CHUNKS];     // per-chunk sums for 2-level scan
__device__ __align__(8)  int2  g_csr[N_EDGES];      // (src, norm as float bits)
__device__ __align__(16) float g_h[N_NODES * D];    // GEMM output / message source

// ---------------------------------------------------------------------------
// Init: deg = 1 (self-loop), cnt = 0
// ---------------------------------------------------------------------------
__global__ void init_kernel() {
    int i = blockIdx.x * blockDim.x + threadIdx.x;
    if (i < N_NODES) { g_deg[i] = 1.0f; g_cnt[i] = 0; }
}

// Histogram: per-edge, count + weighted degree at dst
__global__ void hist_kernel(const int* __restrict__ ei,
                            const float* __restrict__ ew) {
    int e = blockIdx.x * blockDim.x + threadIdx.x;
    if (e < N_EDGES) {
        int d = ei[N_EDGES + e];
        atomicAdd(&g_cnt[d], 1);
        atomicAdd(&g_deg[d], ew[e]);
    }
}

__global__ void dinv_kernel() {
    int i = blockIdx.x * blockDim.x + threadIdx.x;
    if (i < N_NODES) g_dinv[i] = rsqrtf(g_deg[i]);  // deg >= 1 always
}

// ---------------------------------------------------------------------------
// Two-level exclusive scan of g_cnt -> g_off
// ---------------------------------------------------------------------------
__global__ void scan_reduce_kernel() {            // grid = N_CHUNKS, block = 512
    __shared__ int sh[SCAN_CHUNK];
    int t = threadIdx.x;
    int i = blockIdx.x * SCAN_CHUNK + t;
    sh[t] = (i < N_NODES) ? g_cnt[i] : 0;
    __syncthreads();
    for (int off = SCAN_CHUNK / 2; off > 0; off >>= 1) {
        if (t < off) sh[t] += sh[t + off];
        __syncthreads();
    }
    if (t == 0) g_bsum[blockIdx.x] = sh[0];
}

__global__ void scan_tops_kernel() {              // 1 block, 128 threads
    __shared__ int sh[128];
    int t = threadIdx.x;
    int v = (t < N_CHUNKS) ? g_bsum[t] : 0;
    sh[t] = v;
    __syncthreads();
    for (int off = 1; off < 128; off <<= 1) {
        int add = (t >= off) ? sh[t - off] : 0;
        __syncthreads();
        sh[t] += add;
        __syncthreads();
    }
    if (t < N_CHUNKS) g_bsum[t] = sh[t] - v;      // exclusive
}

__global__ void scan_final_kernel() {             // grid = N_CHUNKS, block = 512
    __shared__ int sh[SCAN_CHUNK];
    int t = threadIdx.x;
    int i = blockIdx.x * SCAN_CHUNK + t;
    int v = (i < N_NODES) ? g_cnt[i] : 0;
    sh[t] = v;
    __syncthreads();
    for (int off = 1; off < SCAN_CHUNK; off <<= 1) {
        int add = (t >= off) ? sh[t - off] : 0;
        __syncthreads();
        sh[t] += add;
        __syncthreads();
    }
    if (i < N_NODES) {
        int excl = sh[t] - v + g_bsum[blockIdx.x];
        g_off[i] = excl;
        g_cur[i] = excl;
    }
}

// ---------------------------------------------------------------------------
// CSR fill: (src, norm) pairs grouped by dst
// ---------------------------------------------------------------------------
__global__ void fill_kernel(const int* __restrict__ ei,
                            const float* __restrict__ ew) {
    int e = blockIdx.x * blockDim.x + threadIdx.x;
    if (e >= N_EDGES) return;
    int s = ei[e];
    int d = ei[N_EDGES + e];
    float nrm = g_dinv[s] * ew[e] * g_dinv[d];
    int pos = atomicAdd(&g_cur[d], 1);
    g_csr[pos] = make_int2(s, __float_as_int(nrm));
}

// ---------------------------------------------------------------------------
// GEMM: g_h = (relu?)(X) @ W   X:[N,64] W:[64,64]
// One thread per row; W broadcast from shared; 64 fp32 accumulators.
// ---------------------------------------------------------------------------
template <bool RELU_IN>
__global__ void gemm_kernel(const float* __restrict__ X,
                            const float* __restrict__ W) {
    __shared__ float Ws[D * D];
    int tid = threadIdx.x;
    for (int i = tid; i < D * D; i += 256) Ws[i] = W[i];
    __syncthreads();

    int r = blockIdx.x * 256 + tid;
    if (r >= N_NODES) return;

    const float* xr = X + (size_t)r * D;

    float acc[D];
#pragma unroll
    for (int c = 0; c < D; c++) acc[c] = 0.0f;

#pragma unroll 4
    for (int k = 0; k < D; k++) {
        float xv = xr[k];
        if (RELU_IN) xv = fmaxf(xv, 0.0f);
#pragma unroll
        for (int c = 0; c < D; c++) acc[c] = fmaf(xv, Ws[k * D + c], acc[c]);
    }

    float4* hp = (float4*)(g_h + (size_t)r * D);
#pragma unroll
    for (int c = 0; c < D / 4; c++)
        hp[c] = make_float4(acc[4 * c], acc[4 * c + 1], acc[4 * c + 2], acc[4 * c + 3]);
}

// ---------------------------------------------------------------------------
// Gather-aggregate: one warp per dst node.
// lane l accumulates columns l and l+32; self-loop + bias folded in.
// out[n, :] = sum_{e in in(n)} norm_e * h[src_e, :] + dinv[n]^2 * h[n, :] + b
// ---------------------------------------------------------------------------
__global__ void aggregate_kernel(const float* __restrict__ b,
                                 float* __restrict__ out) {
    int warp = (blockIdx.x * blockDim.x + threadIdx.x) >> 5;
    int lane = threadIdx.x & 31;
    if (warp >= N_NODES) return;
    int n = warp;

    float dv = g_dinv[n];
    float sn = dv * dv;

    const float* hn = g_h + (size_t)n * D;
    float a0 = fmaf(sn, hn[lane],      b[lane]);
    float a1 = fmaf(sn, hn[lane + 32], b[lane + 32]);

    int beg = g_off[n];
    int cnt = g_cnt[n];

    const int2* csr = g_csr + beg;
#pragma unroll 2
    for (int j = 0; j < cnt; j++) {
        int2 p = csr[j];                       // uniform across warp
        int s = p.x;
        float nrm = __int_as_float(p.y);
        const float* hs = g_h + (size_t)s * D;
        a0 = fmaf(nrm, hs[lane],      a0);
        a1 = fmaf(nrm, hs[lane + 32], a1);
    }

    float* op = out + (size_t)n * D;
    op[lane]      = a0;
    op[lane + 32] = a1;
}

// ---------------------------------------------------------------------------
// Final ReLU in-place
// ---------------------------------------------------------------------------
__global__ void relu_out_kernel(float* out) {
    int idx = blockIdx.x * blockDim.x + threadIdx.x;
    if (idx >= N_NODES * D) return;
    out[idx] = fmaxf(out[idx], 0.0f);
}

// ---------------------------------------------------------------------------
extern "C" void kernel_launch(void* const* d_in, const int* in_sizes, int n_in,
                              void* d_out, int out_size) {
    const float* x  = (const float*)d_in[0];
    const int*   ei = (const int*)d_in[1];
    const float* ew = (const float*)d_in[2];
    const float* W0 = (const float*)d_in[3];
    const float* b0 = (const float*)d_in[4];
    const float* W1 = (const float*)d_in[5];
    const float* b1 = (const float*)d_in[6];
    const float* W2 = (const float*)d_in[7];
    const float* b2 = (const float*)d_in[8];
    float* out = (float*)d_out;

    const int TB = 256;
    const int gN   = (N_NODES + TB - 1) / TB;            // 196
    const int gE   = (N_EDGES + TB - 1) / TB;            // 3125
    const int gW   = (N_NODES * 32 + TB - 1) / TB;       // 6250 (warp/node)
    const int gND  = (N_NODES * D + TB - 1) / TB;        // 12500

    // ---- CSR build (once per call) ----
    init_kernel<<<gN, TB>>>();
    hist_kernel<<<gE, TB>>>(ei, ew);
    dinv_kernel<<<gN, TB>>>();
    scan_reduce_kernel<<<N_CHUNKS, SCAN_CHUNK>>>();
    scan_tops_kernel<<<1, 128>>>();
    scan_final_kernel<<<N_CHUNKS, SCAN_CHUNK>>>();
    fill_kernel<<<gE, TB>>>(ei, ew);

    // ---- layer 0 ----
    gemm_kernel<false><<<gN, TB>>>(x, W0);
    aggregate_kernel<<<gW, TB>>>(b0, out);

    // ---- layer 1 ----
    gemm_kernel<true><<<gN, TB>>>(out, W1);
    aggregate_kernel<<<gW, TB>>>(b1, out);

    // ---- layer 2 ----
    gemm_kernel<true><<<gN, TB>>>(out, W2);
    aggregate_kernel<<<gW, TB>>>(b2, out);

    relu_out_kernel<<<gND, TB>>>(out);
}